// round 4
// baseline (speedup 1.0000x reference)
#include <cuda_runtime.h>
#include <cuda_bf16.h>
#include <math.h>
#include <complex>
#include <algorithm>

// Problem: RS=[(16,0),(16,1)] -> N_DIM=64, N_PATH=1536, RADIAL_H=64
// points = 16*32*32 = 16384; out = points * 64*64 fp32.

#define NPOINTS 16384
#define GPTS    16
#define NBLK    (NPOINTS / GPTS)
#define NPATH   1536

struct Consts {
    float cg000;
    float cg011[3][3];   // real3j(0,1,1)[0][j][k]
    float cg101[3][3];   // real3j(1,0,1)[i][0][k]
    float cg110[3][3];   // real3j(1,1,0)[i][j][0]
    float cg111[3][3][3];
    float cg112[3][3][5];
    float nrm[2][2][2];
};

// W2 permuted + pair-duplicated: index o = (((s*16+kq)*2+L)*256+t)*4+j,
// e = 2L + (j>>1), k = kq*4+e, col(s,t). 768 KB scratch.
__device__ float g_W2Pd[2 * 64 * NPATH];

__global__ void permute_w2(const float* __restrict__ W2) {
    int o = blockIdx.x * blockDim.x + threadIdx.x;
    if (o >= 2 * 64 * NPATH) return;
    int j  = o & 3;
    int t  = (o >> 2) & 255;
    int L  = (o >> 10) & 1;
    int kq = (o >> 11) & 15;
    int s  = o >> 15;
    int e  = 2 * L + (j >> 1);
    int k  = kq * 4 + e;
    int col = (s < 3) ? (s * 256 + t) : (768 + 3 * t + (s - 3));
    g_W2Pd[o] = W2[k * NPATH + col];
}

__device__ __forceinline__ unsigned long long fma2(unsigned long long a,
                                                   unsigned long long b,
                                                   unsigned long long c) {
    unsigned long long d;
    asm("fma.rn.f32x2 %0, %1, %2, %3;" : "=l"(d) : "l"(a), "l"(b), "l"(c));
    return d;
}
__device__ __forceinline__ unsigned long long pack2(float lo, float hi) {
    unsigned long long d;
    asm("mov.b64 %0, {%1, %2};" : "=l"(d) : "f"(lo), "f"(hi));
    return d;
}
__device__ __forceinline__ void unpack2(unsigned long long v, float& lo, float& hi) {
    asm("mov.b64 {%0, %1}, %2;" : "=f"(lo), "=f"(hi) : "l"(v));
}

__global__ __launch_bounds__(256, 1)
void qm9_fused(const float* __restrict__ r,
               const float* __restrict__ W1,
               const float* __restrict__ b1,
               const float* __restrict__ b2,
               float* __restrict__ out,
               const Consts C)
{
    __shared__ __align__(16) float sh_hT[64][16];  // [k][p]
    __shared__ float sh_pp[GPTS][36];
    __shared__ float sh_rad[GPTS];

    const int t = threadIdx.x;
    const int block0 = blockIdx.x * GPTS;

    // ---- Phase A: per-point SH + folded CG*Y*norm (threads 0..15) ----
    if (t < GPTS) {
        int pg = block0 + t;
        float x = r[pg * 3 + 0], y = r[pg * 3 + 1], z = r[pg * 3 + 2];
        float r2 = x * x + y * y + z * z;
        sh_rad[t] = sqrtf(r2);
        float inv  = rsqrtf(r2);
        float inv2 = 1.0f / r2;
        const float c0  = 0.28209479177387814f;
        const float c1  = 0.48860251190291992f;
        const float c2  = 1.09254843059207907f;
        const float c20 = 0.31539156525252005f;
        float Y[9];
        Y[0] = c0;
        Y[1] = c1 * y * inv;
        Y[2] = c1 * z * inv;
        Y[3] = c1 * x * inv;
        Y[4] = c2 * x * y * inv2;
        Y[5] = c2 * y * z * inv2;
        Y[6] = c20 * (3.0f * z * z - r2) * inv2;
        Y[7] = c2 * x * z * inv2;
        Y[8] = 0.5f * c2 * (x * x - y * y) * inv2;

        int zf = (r2 == 0.0f) ? 1 : 0;
        float s00 = C.nrm[0][0][zf], s01 = C.nrm[0][1][zf];
        float s10 = C.nrm[1][0][zf], s11 = C.nrm[1][1][zf];

        sh_pp[t][0] = C.cg000 * Y[0] * s00;
        #pragma unroll
        for (int j = 0; j < 3; j++) {
            float a = 0.f;
            #pragma unroll
            for (int k = 0; k < 3; k++) a += C.cg011[j][k] * Y[1 + k];
            sh_pp[t][1 + j] = a * s01;
        }
        #pragma unroll
        for (int i = 0; i < 3; i++) {
            float a = 0.f;
            #pragma unroll
            for (int k = 0; k < 3; k++) a += C.cg101[i][k] * Y[1 + k];
            sh_pp[t][4 + i] = a * s10;
        }
        #pragma unroll
        for (int i = 0; i < 3; i++) {
            #pragma unroll
            for (int j = 0; j < 3; j++) {
                sh_pp[t][7 + i * 3 + j] = C.cg110[i][j] * Y[0] * s11;
                float a1 = 0.f;
                #pragma unroll
                for (int k = 0; k < 3; k++) a1 += C.cg111[i][j][k] * Y[1 + k];
                sh_pp[t][16 + i * 3 + j] = a1 * s11;
                float a2 = 0.f;
                #pragma unroll
                for (int k = 0; k < 5; k++) a2 += C.cg112[i][j][k] * Y[4 + k];
                sh_pp[t][25 + i * 3 + j] = a2 * s11;
            }
        }
    }
    __syncthreads();

    // ---- Phase B: h = silu(rad*W1+b1), stored transposed [k][p] ----
    {
        int p  = t & 15;
        int k0 = (t >> 4) * 4;
        float rad = sh_rad[p];
        #pragma unroll
        for (int e = 0; e < 4; e++) {
            float xx = fmaf(rad, W1[k0 + e], b1[k0 + e]);
            sh_hT[k0 + e][p] = xx / (1.0f + expf(-xx));
        }
    }
    __syncthreads();

    // ---- Phase C: packed GEMM. acc2[pair][s] holds points (2*pair, 2*pair+1) ----
    unsigned long long acc2[8][6];
    #pragma unroll
    for (int pr = 0; pr < 8; pr++)
        #pragma unroll
        for (int s = 0; s < 6; s++) acc2[pr][s] = 0ull;

    const ulonglong2* w2p = (const ulonglong2*)g_W2Pd + t;  // stride per slot: 256
    const float4* shT4 = (const float4*)sh_hT;              // [k*4 + q]

    #pragma unroll 1
    for (int kq = 0; kq < 16; kq++) {
        ulonglong2 wv[6][2];
        #pragma unroll
        for (int s = 0; s < 6; s++) {
            wv[s][0] = w2p[((s * 16 + kq) * 2 + 0) * 256];
            wv[s][1] = w2p[((s * 16 + kq) * 2 + 1) * 256];
        }
        #pragma unroll
        for (int q = 0; q < 4; q++) {
            #pragma unroll
            for (int e = 0; e < 4; e++) {
                float4 hv = shT4[(kq * 4 + e) * 4 + q];
                unsigned long long h01 = pack2(hv.x, hv.y);
                unsigned long long h23 = pack2(hv.z, hv.w);
                #pragma unroll
                for (int s = 0; s < 6; s++) {
                    unsigned long long wp = (e & 1) ? wv[s][e >> 1].y : wv[s][e >> 1].x;
                    acc2[2 * q + 0][s] = fma2(h01, wp, acc2[2 * q + 0][s]);
                    acc2[2 * q + 1][s] = fma2(h23, wp, acc2[2 * q + 1][s]);
                }
            }
        }
    }

    // ---- Phase D: epilogue ----
    float b2v[6];
    b2v[0] = b2[t];
    b2v[1] = b2[256 + t];
    b2v[2] = b2[512 + t];
    b2v[3] = b2[768 + 3 * t + 0];
    b2v[4] = b2[768 + 3 * t + 1];
    b2v[5] = b2[768 + 3 * t + 2];

    const int u = t >> 4, v = t & 15;

    #pragma unroll 1
    for (int pr = 0; pr < 8; pr++) {
        float Rl[6], Rh[6];
        #pragma unroll
        for (int s = 0; s < 6; s++) {
            float lo, hi;
            unpack2(acc2[pr][s], lo, hi);
            Rl[s] = lo + b2v[s];
            Rh[s] = hi + b2v[s];
        }
        #pragma unroll
        for (int half = 0; half < 2; half++) {
            int p = 2 * pr + half;
            const float* Rv = half ? Rh : Rl;
            float* o = out + (size_t)(block0 + p) * 4096;
            const float* pp = sh_pp[p];

            o[u * 64 + v] = pp[0] * Rv[0];
            #pragma unroll
            for (int j = 0; j < 3; j++)
                o[u * 64 + 16 + 3 * v + j] = pp[1 + j] * Rv[1];
            #pragma unroll
            for (int i = 0; i < 3; i++)
                o[(16 + 3 * u + i) * 64 + v] = pp[4 + i] * Rv[2];
            #pragma unroll
            for (int i = 0; i < 3; i++) {
                #pragma unroll
                for (int j = 0; j < 3; j++) {
                    float val = pp[7  + i * 3 + j] * Rv[3]
                              + pp[16 + i * 3 + j] * Rv[4]
                              + pp[25 + i * 3 + j] * Rv[5];
                    o[(16 + 3 * u + i) * 64 + 16 + 3 * v + j] = val;
                }
            }
        }
    }
}

// ===========================================================================
// Host: exact replication of the reference real-3j / norm constants.
// ===========================================================================
static double dfact_(int n) { double r = 1.0; for (int i = 2; i <= n; i++) r *= i; return r; }

static double su2_cg_(int j1, int m1, int j2, int m2, int j3, int m3) {
    if (m3 != m1 + m2) return 0.0;
    int vmin = std::max(std::max(-j1 + j2 + m3, -j1 + m1), 0);
    int vmax = std::min(std::min(j2 + j3 + m1, j3 - j1 + j2), j3 + m3);
    double c = sqrt((2 * j3 + 1) * dfact_(j3 + j1 - j2) * dfact_(j3 - j1 + j2) *
                    dfact_(j1 + j2 - j3) / dfact_(j1 + j2 + j3 + 1)) *
               sqrt(dfact_(j3 + m3) * dfact_(j3 - m3) /
                    (dfact_(j1 + m1) * dfact_(j1 - m1) * dfact_(j2 + m2) * dfact_(j2 - m2)));
    double s = 0.0;
    for (int v = vmin; v <= vmax; v++) {
        double sg = ((v + j2 + m2) & 1) ? -1.0 : 1.0;
        s += sg * dfact_(j2 + j3 + m1 - v) * dfact_(j1 - m1 + v) /
             (dfact_(v) * dfact_(j3 - j1 + j2 - v) * dfact_(j3 + m3 - v) *
              dfact_(v + j1 - j2 - m3));
    }
    return c * s;
}

static void Qmat_(int l, std::complex<double> q[5][5]) {
    for (int i = 0; i < 5; i++) for (int j = 0; j < 5; j++) q[i][j] = 0.0;
    q[l][l] = 1.0;
    double s2 = 1.0 / sqrt(2.0);
    for (int m = 1; m <= l; m++) {
        double pm = (m & 1) ? -1.0 : 1.0;
        q[l + m][l - m] = s2;
        q[l + m][l + m] = pm * s2;
        q[l - m][l - m] = std::complex<double>(0.0, s2);
        q[l - m][l + m] = std::complex<double>(0.0, -pm * s2);
    }
}

static void real3j_(int l1, int l2, int l3, double outc[5][5][5]) {
    int d1 = 2 * l1 + 1, d2 = 2 * l2 + 1, d3 = 2 * l3 + 1;
    double w[5][5][5];
    for (int i = 0; i < 5; i++) for (int j = 0; j < 5; j++) for (int k = 0; k < 5; k++)
        w[i][j][k] = 0.0;
    for (int m1 = -l1; m1 <= l1; m1++)
        for (int m2 = -l2; m2 <= l2; m2++) {
            int m3 = -(m1 + m2);
            if (m3 < -l3 || m3 > l3) continue;
            double sg = ((l1 - l2 + m1 + m2) & 1) ? -1.0 : 1.0;
            w[m1 + l1][m2 + l2][m3 + l3] =
                sg / sqrt((double)(2 * l3 + 1)) * su2_cg_(l1, m1, l2, m2, l3, -m3);
        }
    std::complex<double> q1[5][5], q2[5][5], q3[5][5];
    Qmat_(l1, q1); Qmat_(l2, q2); Qmat_(l3, q3);
    std::complex<double> Cc[5][5][5];
    for (int a = 0; a < d1; a++)
        for (int b = 0; b < d2; b++)
            for (int c = 0; c < d3; c++) {
                std::complex<double> s = 0.0;
                for (int i = 0; i < d1; i++)
                    for (int j = 0; j < d2; j++)
                        for (int k = 0; k < d3; k++)
                            s += q1[a][i] * q2[b][j] * q3[c][k] * w[i][j][k];
                Cc[a][b][c] = s;
            }
    // phase fix: first flat index within tolerance of max |C| (numpy argmax semantics)
    double maxv = 0.0;
    for (int a = 0; a < d1; a++) for (int b = 0; b < d2; b++) for (int c = 0; c < d3; c++)
        maxv = std::max(maxv, std::abs(Cc[a][b][c]));
    std::complex<double> ph = 0.0;
    for (int a = 0; a < d1 && ph == 0.0; a++)
        for (int b = 0; b < d2 && ph == 0.0; b++)
            for (int c = 0; c < d3 && ph == 0.0; c++)
                if (std::abs(Cc[a][b][c]) >= maxv * (1.0 - 1e-9)) ph = Cc[a][b][c];
    for (int i = 0; i < 5; i++) for (int j = 0; j < 5; j++) for (int k = 0; k < 5; k++)
        outc[i][j][k] = 0.0;
    if (std::abs(ph) < 1e-12) {
        for (int a = 0; a < d1; a++) for (int b = 0; b < d2; b++) for (int c = 0; c < d3; c++)
            outc[a][b][c] = Cc[a][b][c].real();
    } else {
        std::complex<double> u = ph / std::abs(ph);
        for (int a = 0; a < d1; a++) for (int b = 0; b < d2; b++) for (int c = 0; c < d3; c++)
            outc[a][b][c] = (Cc[a][b][c] / u).real();
    }
}

extern "C" void kernel_launch(void* const* d_in, const int* in_sizes, int n_in,
                              void* d_out, int out_size) {
    const float* r  = (const float*)d_in[0];
    const float* W1 = (const float*)d_in[1];
    const float* b1 = (const float*)d_in[2];
    const float* W2 = (const float*)d_in[3];
    const float* b2 = (const float*)d_in[4];
    float* out = (float*)d_out;

    Consts C;
    double tmp[5][5][5];
    real3j_(0, 0, 0, tmp); C.cg000 = (float)tmp[0][0][0];
    real3j_(0, 1, 1, tmp);
    for (int j = 0; j < 3; j++) for (int k = 0; k < 3; k++) C.cg011[j][k] = (float)tmp[0][j][k];
    real3j_(1, 0, 1, tmp);
    for (int i = 0; i < 3; i++) for (int k = 0; k < 3; k++) C.cg101[i][k] = (float)tmp[i][0][k];
    real3j_(1, 1, 0, tmp);
    for (int i = 0; i < 3; i++) for (int j = 0; j < 3; j++) C.cg110[i][j] = (float)tmp[i][j][0];
    real3j_(1, 1, 1, tmp);
    for (int i = 0; i < 3; i++) for (int j = 0; j < 3; j++) for (int k = 0; k < 3; k++)
        C.cg111[i][j][k] = (float)tmp[i][j][k];
    real3j_(1, 1, 2, tmp);
    for (int i = 0; i < 3; i++) for (int j = 0; j < 3; j++) for (int k = 0; k < 5; k++)
        C.cg112[i][j][k] = (float)tmp[i][j][k];

    // NORM[i][j][zf]: lm = sqrt(2*li+1)*sqrt(4*pi); nse_i = {32, 64}
    const double fourpi = 4.0 * M_PI;
    double nse[2] = {32.0, 64.0};
    for (int i = 0; i < 2; i++)
        for (int j = 0; j < 2; j++) {
            double li = (j == 0) ? 0.0 : 1.0;
            double lm = sqrt(2.0 * li + 1.0) * sqrt(fourpi);
            C.nrm[i][j][0] = (float)(lm / sqrt(nse[i]));
            C.nrm[i][j][1] = (float)(lm / sqrt(16.0));
        }

    permute_w2<<<(2 * 64 * NPATH + 255) / 256, 256>>>(W2);
    qm9_fused<<<NBLK, 256>>>(r, W1, b1, b2, out, C);
}

// round 5
// speedup vs baseline: 1.2710x; 1.2710x over previous
#include <cuda_runtime.h>
#include <cuda_bf16.h>
#include <math.h>
#include <complex>
#include <algorithm>

// Problem: RS=[(16,0),(16,1)] -> N_DIM=64, N_PATH=1536, RADIAL_H=64
// points = 16*32*32 = 16384; out = points * 64*64 fp32.

#define NPOINTS 16384
#define GPTS    16
#define NBLK    (NPOINTS / GPTS)
#define NPATH   1536

struct Consts {
    float cg000;
    float cg011[3][3];   // real3j(0,1,1)[0][j][k]
    float cg101[3][3];   // real3j(1,0,1)[i][0][k]
    float cg110[3][3];   // real3j(1,1,0)[i][j][0]
    float cg111[3][3][3];
    float cg112[3][3][5];
    float nrm[2][2][2];
};

// W2 permuted, s-pair packed over k-pairs (NO duplication, 384 KB):
// float index o = (((sp*32 + k2)*256 + t)*4 + e)
//   e=0: (k=2k2  , s=2sp  )   e=1: (k=2k2  , s=2sp+1)
//   e=2: (k=2k2+1, s=2sp  )   e=3: (k=2k2+1, s=2sp+1)
// col(s,t) = s<3 ? s*256+t : 768+3t+(s-3)
__device__ float g_W2P[64 * NPATH];

__global__ void permute_w2(const float* __restrict__ W2) {
    int o = blockIdx.x * blockDim.x + threadIdx.x;
    if (o >= 64 * NPATH) return;
    int e  = o & 3;
    int t  = (o >> 2) & 255;
    int k2 = (o >> 10) & 31;
    int sp = o >> 15;
    int k  = 2 * k2 + (e >> 1);
    int s  = 2 * sp + (e & 1);
    int col = (s < 3) ? (s * 256 + t) : (768 + 3 * t + (s - 3));
    g_W2P[o] = W2[k * NPATH + col];
}

__device__ __forceinline__ unsigned long long fma2(unsigned long long a,
                                                   unsigned long long b,
                                                   unsigned long long c) {
    unsigned long long d;
    asm("fma.rn.f32x2 %0, %1, %2, %3;" : "=l"(d) : "l"(a), "l"(b), "l"(c));
    return d;
}
__device__ __forceinline__ void unpack2(unsigned long long v, float& lo, float& hi) {
    asm("mov.b64 {%0, %1}, %2;" : "=f"(lo), "=f"(hi) : "l"(v));
}

__global__ __launch_bounds__(256, 1)
void qm9_fused(const float* __restrict__ r,
               const float* __restrict__ W1,
               const float* __restrict__ b1,
               const float* __restrict__ b2,
               float* __restrict__ out,
               const Consts C)
{
    // h duplicated per element: sh_hd[k][p] = (h, h)
    __shared__ __align__(16) float2 sh_hd[64][16];   // 8 KB
    __shared__ float sh_pp[GPTS][36];
    __shared__ float sh_rad[GPTS];
    __shared__ float sR[6][256];                     // per-point R exchange, 6 KB

    const int t = threadIdx.x;
    const int block0 = blockIdx.x * GPTS;

    // ---- Phase A: per-point SH + folded CG*Y*norm (threads 0..15) ----
    if (t < GPTS) {
        int pg = block0 + t;
        float x = r[pg * 3 + 0], y = r[pg * 3 + 1], z = r[pg * 3 + 2];
        float r2 = x * x + y * y + z * z;
        sh_rad[t] = sqrtf(r2);
        float inv  = rsqrtf(r2);
        float inv2 = 1.0f / r2;
        const float c0  = 0.28209479177387814f;
        const float c1  = 0.48860251190291992f;
        const float c2  = 1.09254843059207907f;
        const float c20 = 0.31539156525252005f;
        float Y[9];
        Y[0] = c0;
        Y[1] = c1 * y * inv;
        Y[2] = c1 * z * inv;
        Y[3] = c1 * x * inv;
        Y[4] = c2 * x * y * inv2;
        Y[5] = c2 * y * z * inv2;
        Y[6] = c20 * (3.0f * z * z - r2) * inv2;
        Y[7] = c2 * x * z * inv2;
        Y[8] = 0.5f * c2 * (x * x - y * y) * inv2;

        int zf = (r2 == 0.0f) ? 1 : 0;
        float s00 = C.nrm[0][0][zf], s01 = C.nrm[0][1][zf];
        float s10 = C.nrm[1][0][zf], s11 = C.nrm[1][1][zf];

        sh_pp[t][0] = C.cg000 * Y[0] * s00;
        #pragma unroll
        for (int j = 0; j < 3; j++) {
            float a = 0.f;
            #pragma unroll
            for (int k = 0; k < 3; k++) a += C.cg011[j][k] * Y[1 + k];
            sh_pp[t][1 + j] = a * s01;
        }
        #pragma unroll
        for (int i = 0; i < 3; i++) {
            float a = 0.f;
            #pragma unroll
            for (int k = 0; k < 3; k++) a += C.cg101[i][k] * Y[1 + k];
            sh_pp[t][4 + i] = a * s10;
        }
        #pragma unroll
        for (int i = 0; i < 3; i++) {
            #pragma unroll
            for (int j = 0; j < 3; j++) {
                sh_pp[t][7 + i * 3 + j] = C.cg110[i][j] * Y[0] * s11;
                float a1 = 0.f;
                #pragma unroll
                for (int k = 0; k < 3; k++) a1 += C.cg111[i][j][k] * Y[1 + k];
                sh_pp[t][16 + i * 3 + j] = a1 * s11;
                float a2 = 0.f;
                #pragma unroll
                for (int k = 0; k < 5; k++) a2 += C.cg112[i][j][k] * Y[4 + k];
                sh_pp[t][25 + i * 3 + j] = a2 * s11;
            }
        }
    }
    __syncthreads();

    // ---- Phase B: h = silu(rad*W1+b1), stored duplicated [k][p] = (h,h) ----
    {
        int p  = t & 15;
        int k0 = (t >> 4) * 4;
        float rad = sh_rad[p];
        #pragma unroll
        for (int e = 0; e < 4; e++) {
            float xx = fmaf(rad, W1[k0 + e], b1[k0 + e]);
            float h = xx / (1.0f + expf(-xx));
            sh_hd[k0 + e][p] = make_float2(h, h);
        }
    }
    __syncthreads();

    // ---- Phase C: packed GEMM over s-pairs.
    // acc[p][sp] (u64) = (R_{2sp}(p), R_{2sp+1}(p)) partial sums.
    unsigned long long acc[GPTS][3];
    #pragma unroll
    for (int p = 0; p < GPTS; p++)
        #pragma unroll
        for (int sp = 0; sp < 3; sp++) acc[p][sp] = 0ull;

    const ulonglong2* wp = (const ulonglong2*)g_W2P + t;  // slot stride 256
    const ulonglong2* hp = (const ulonglong2*)sh_hd;      // index k*8 + q

    ulonglong2 wA = wp[(0 * 32 + 0) * 256];
    ulonglong2 wB = wp[(1 * 32 + 0) * 256];
    ulonglong2 wC = wp[(2 * 32 + 0) * 256];

    #pragma unroll 1
    for (int k2 = 0; k2 < 32; k2++) {
        int kn = (k2 < 31) ? (k2 + 1) : 31;
        ulonglong2 nA = wp[(0 * 32 + kn) * 256];
        ulonglong2 nB = wp[(1 * 32 + kn) * 256];
        ulonglong2 nC = wp[(2 * 32 + kn) * 256];

        #pragma unroll
        for (int q = 0; q < 8; q++) {
            ulonglong2 he = hp[(2 * k2 + 0) * 8 + q];   // (h_dup p=2q, h_dup p=2q+1), k even
            ulonglong2 ho = hp[(2 * k2 + 1) * 8 + q];   // k odd
            // k even
            acc[2 * q + 0][0] = fma2(he.x, wA.x, acc[2 * q + 0][0]);
            acc[2 * q + 0][1] = fma2(he.x, wB.x, acc[2 * q + 0][1]);
            acc[2 * q + 0][2] = fma2(he.x, wC.x, acc[2 * q + 0][2]);
            acc[2 * q + 1][0] = fma2(he.y, wA.x, acc[2 * q + 1][0]);
            acc[2 * q + 1][1] = fma2(he.y, wB.x, acc[2 * q + 1][1]);
            acc[2 * q + 1][2] = fma2(he.y, wC.x, acc[2 * q + 1][2]);
            // k odd
            acc[2 * q + 0][0] = fma2(ho.x, wA.y, acc[2 * q + 0][0]);
            acc[2 * q + 0][1] = fma2(ho.x, wB.y, acc[2 * q + 0][1]);
            acc[2 * q + 0][2] = fma2(ho.x, wC.y, acc[2 * q + 0][2]);
            acc[2 * q + 1][0] = fma2(ho.y, wA.y, acc[2 * q + 1][0]);
            acc[2 * q + 1][1] = fma2(ho.y, wB.y, acc[2 * q + 1][1]);
            acc[2 * q + 1][2] = fma2(ho.y, wC.y, acc[2 * q + 1][2]);
        }
        wA = nA; wB = nB; wC = nC;
    }

    // ---- Phase D: coalesced epilogue via smem R-exchange ----
    float b2v[6];
    b2v[0] = b2[t];
    b2v[1] = b2[256 + t];
    b2v[2] = b2[512 + t];
    b2v[3] = b2[768 + 3 * t + 0];
    b2v[4] = b2[768 + 3 * t + 1];
    b2v[5] = b2[768 + 3 * t + 2];

    // Thread t writes float4 #(m*256+t) of each point's 4096-float block:
    //   row = m*16 + (t>>4), cols = 4*(t&15)+{0..3}
    const int tu = t >> 4;      // 0..15
    const int c  = t & 15;      // col chunk

    // precompute (v, j) for cols >= 16 (c >= 4); unused otherwise
    int vd0 = 0, vd1 = 0, vd2 = 0, vd3 = 0, jd0 = 0, jd1 = 0, jd2 = 0, jd3 = 0;
    if (c >= 4) {
        int base = 4 * (c - 4);
        vd0 = (base + 0) / 3; jd0 = (base + 0) - 3 * vd0;
        vd1 = (base + 1) / 3; jd1 = (base + 1) - 3 * vd1;
        vd2 = (base + 2) / 3; jd2 = (base + 2) - 3 * vd2;
        vd3 = (base + 3) / 3; jd3 = (base + 3) - 3 * vd3;
    }
    // precompute (u2, i) for m = 1..3 (rows >= 16)
    int um[4], im[4];
    #pragma unroll
    for (int m = 1; m < 4; m++) {
        int rr = (m - 1) * 16 + tu;
        um[m] = rr / 3;
        im[m] = rr - 3 * um[m];
    }

    #pragma unroll 1
    for (int p = 0; p < GPTS; p++) {
        float R[6];
        unpack2(acc[p][0], R[0], R[1]);
        unpack2(acc[p][1], R[2], R[3]);
        unpack2(acc[p][2], R[4], R[5]);
        #pragma unroll
        for (int s = 0; s < 6; s++) sR[s][t] = R[s] + b2v[s];
        __syncthreads();

        const float* pp = sh_pp[p];
        float* o = out + (size_t)(block0 + p) * 4096;

        #pragma unroll
        for (int m = 0; m < 4; m++) {
            float v0, v1, v2, v3;
            if (m == 0) {
                if (c < 4) {
                    const float* s0 = &sR[0][tu * 16 + 4 * c];
                    float sc = pp[0];
                    v0 = sc * s0[0]; v1 = sc * s0[1]; v2 = sc * s0[2]; v3 = sc * s0[3];
                } else {
                    const float* s1 = &sR[1][tu * 16];
                    v0 = pp[1 + jd0] * s1[vd0];
                    v1 = pp[1 + jd1] * s1[vd1];
                    v2 = pp[1 + jd2] * s1[vd2];
                    v3 = pp[1 + jd3] * s1[vd3];
                }
            } else {
                int u2 = um[m], i = im[m];
                if (c < 4) {
                    const float* s2 = &sR[2][u2 * 16 + 4 * c];
                    float sc = pp[4 + i];
                    v0 = sc * s2[0]; v1 = sc * s2[1]; v2 = sc * s2[2]; v3 = sc * s2[3];
                } else {
                    const float* s3 = &sR[3][u2 * 16];
                    const float* s4 = &sR[4][u2 * 16];
                    const float* s5 = &sR[5][u2 * 16];
                    const float* pa = pp + 7  + 3 * i;
                    const float* pb = pp + 16 + 3 * i;
                    const float* pc = pp + 25 + 3 * i;
                    v0 = pa[jd0] * s3[vd0] + pb[jd0] * s4[vd0] + pc[jd0] * s5[vd0];
                    v1 = pa[jd1] * s3[vd1] + pb[jd1] * s4[vd1] + pc[jd1] * s5[vd1];
                    v2 = pa[jd2] * s3[vd2] + pb[jd2] * s4[vd2] + pc[jd2] * s5[vd2];
                    v3 = pa[jd3] * s3[vd3] + pb[jd3] * s4[vd3] + pc[jd3] * s5[vd3];
                }
            }
            ((float4*)o)[m * 256 + t] = make_float4(v0, v1, v2, v3);
        }
        __syncthreads();
    }
}

// ===========================================================================
// Host: exact replication of the reference real-3j / norm constants.
// ===========================================================================
static double dfact_(int n) { double r = 1.0; for (int i = 2; i <= n; i++) r *= i; return r; }

static double su2_cg_(int j1, int m1, int j2, int m2, int j3, int m3) {
    if (m3 != m1 + m2) return 0.0;
    int vmin = std::max(std::max(-j1 + j2 + m3, -j1 + m1), 0);
    int vmax = std::min(std::min(j2 + j3 + m1, j3 - j1 + j2), j3 + m3);
    double c = sqrt((2 * j3 + 1) * dfact_(j3 + j1 - j2) * dfact_(j3 - j1 + j2) *
                    dfact_(j1 + j2 - j3) / dfact_(j1 + j2 + j3 + 1)) *
               sqrt(dfact_(j3 + m3) * dfact_(j3 - m3) /
                    (dfact_(j1 + m1) * dfact_(j1 - m1) * dfact_(j2 + m2) * dfact_(j2 - m2)));
    double s = 0.0;
    for (int v = vmin; v <= vmax; v++) {
        double sg = ((v + j2 + m2) & 1) ? -1.0 : 1.0;
        s += sg * dfact_(j2 + j3 + m1 - v) * dfact_(j1 - m1 + v) /
             (dfact_(v) * dfact_(j3 - j1 + j2 - v) * dfact_(j3 + m3 - v) *
              dfact_(v + j1 - j2 - m3));
    }
    return c * s;
}

static void Qmat_(int l, std::complex<double> q[5][5]) {
    for (int i = 0; i < 5; i++) for (int j = 0; j < 5; j++) q[i][j] = 0.0;
    q[l][l] = 1.0;
    double s2 = 1.0 / sqrt(2.0);
    for (int m = 1; m <= l; m++) {
        double pm = (m & 1) ? -1.0 : 1.0;
        q[l + m][l - m] = s2;
        q[l + m][l + m] = pm * s2;
        q[l - m][l - m] = std::complex<double>(0.0, s2);
        q[l - m][l + m] = std::complex<double>(0.0, -pm * s2);
    }
}

static void real3j_(int l1, int l2, int l3, double outc[5][5][5]) {
    int d1 = 2 * l1 + 1, d2 = 2 * l2 + 1, d3 = 2 * l3 + 1;
    double w[5][5][5];
    for (int i = 0; i < 5; i++) for (int j = 0; j < 5; j++) for (int k = 0; k < 5; k++)
        w[i][j][k] = 0.0;
    for (int m1 = -l1; m1 <= l1; m1++)
        for (int m2 = -l2; m2 <= l2; m2++) {
            int m3 = -(m1 + m2);
            if (m3 < -l3 || m3 > l3) continue;
            double sg = ((l1 - l2 + m1 + m2) & 1) ? -1.0 : 1.0;
            w[m1 + l1][m2 + l2][m3 + l3] =
                sg / sqrt((double)(2 * l3 + 1)) * su2_cg_(l1, m1, l2, m2, l3, -m3);
        }
    std::complex<double> q1[5][5], q2[5][5], q3[5][5];
    Qmat_(l1, q1); Qmat_(l2, q2); Qmat_(l3, q3);
    std::complex<double> Cc[5][5][5];
    for (int a = 0; a < d1; a++)
        for (int b = 0; b < d2; b++)
            for (int c = 0; c < d3; c++) {
                std::complex<double> s = 0.0;
                for (int i = 0; i < d1; i++)
                    for (int j = 0; j < d2; j++)
                        for (int k = 0; k < d3; k++)
                            s += q1[a][i] * q2[b][j] * q3[c][k] * w[i][j][k];
                Cc[a][b][c] = s;
            }
    double maxv = 0.0;
    for (int a = 0; a < d1; a++) for (int b = 0; b < d2; b++) for (int c = 0; c < d3; c++)
        maxv = std::max(maxv, std::abs(Cc[a][b][c]));
    std::complex<double> ph = 0.0;
    for (int a = 0; a < d1 && ph == 0.0; a++)
        for (int b = 0; b < d2 && ph == 0.0; b++)
            for (int c = 0; c < d3 && ph == 0.0; c++)
                if (std::abs(Cc[a][b][c]) >= maxv * (1.0 - 1e-9)) ph = Cc[a][b][c];
    for (int i = 0; i < 5; i++) for (int j = 0; j < 5; j++) for (int k = 0; k < 5; k++)
        outc[i][j][k] = 0.0;
    if (std::abs(ph) < 1e-12) {
        for (int a = 0; a < d1; a++) for (int b = 0; b < d2; b++) for (int c = 0; c < d3; c++)
            outc[a][b][c] = Cc[a][b][c].real();
    } else {
        std::complex<double> u = ph / std::abs(ph);
        for (int a = 0; a < d1; a++) for (int b = 0; b < d2; b++) for (int c = 0; c < d3; c++)
            outc[a][b][c] = (Cc[a][b][c] / u).real();
    }
}

extern "C" void kernel_launch(void* const* d_in, const int* in_sizes, int n_in,
                              void* d_out, int out_size) {
    const float* r  = (const float*)d_in[0];
    const float* W1 = (const float*)d_in[1];
    const float* b1 = (const float*)d_in[2];
    const float* W2 = (const float*)d_in[3];
    const float* b2 = (const float*)d_in[4];
    float* out = (float*)d_out;

    Consts C;
    double tmp[5][5][5];
    real3j_(0, 0, 0, tmp); C.cg000 = (float)tmp[0][0][0];
    real3j_(0, 1, 1, tmp);
    for (int j = 0; j < 3; j++) for (int k = 0; k < 3; k++) C.cg011[j][k] = (float)tmp[0][j][k];
    real3j_(1, 0, 1, tmp);
    for (int i = 0; i < 3; i++) for (int k = 0; k < 3; k++) C.cg101[i][k] = (float)tmp[i][0][k];
    real3j_(1, 1, 0, tmp);
    for (int i = 0; i < 3; i++) for (int j = 0; j < 3; j++) C.cg110[i][j] = (float)tmp[i][j][0];
    real3j_(1, 1, 1, tmp);
    for (int i = 0; i < 3; i++) for (int j = 0; j < 3; j++) for (int k = 0; k < 3; k++)
        C.cg111[i][j][k] = (float)tmp[i][j][k];
    real3j_(1, 1, 2, tmp);
    for (int i = 0; i < 3; i++) for (int j = 0; j < 3; j++) for (int k = 0; k < 5; k++)
        C.cg112[i][j][k] = (float)tmp[i][j][k];

    const double fourpi = 4.0 * M_PI;
    double nse[2] = {32.0, 64.0};
    for (int i = 0; i < 2; i++)
        for (int j = 0; j < 2; j++) {
            double li = (j == 0) ? 0.0 : 1.0;
            double lm = sqrt(2.0 * li + 1.0) * sqrt(fourpi);
            C.nrm[i][j][0] = (float)(lm / sqrt(nse[i]));
            C.nrm[i][j][1] = (float)(lm / sqrt(16.0));
        }

    permute_w2<<<(64 * NPATH + 255) / 256, 256>>>(W2);
    qm9_fused<<<NBLK, 256>>>(r, W1, b1, b2, out, C);
}

// round 6
// speedup vs baseline: 1.7453x; 1.3731x over previous
#include <cuda_runtime.h>
#include <cuda_bf16.h>
#include <math.h>
#include <complex>
#include <algorithm>

// Problem: RS=[(16,0),(16,1)] -> N_DIM=64, N_PATH=1536, RADIAL_H=64
// points = 16*32*32 = 16384; out = points * 64*64 fp32.

#define NPOINTS 16384
#define GPTS    16
#define NBLK    (NPOINTS / GPTS)
#define NPATH   1536

struct Consts {
    float cg000;
    float cg011[3][3];   // real3j(0,1,1)[0][j][k]
    float cg101[3][3];   // real3j(1,0,1)[i][0][k]
    float cg110[3][3];   // real3j(1,1,0)[i][j][0]
    float cg111[3][3][3];
    float cg112[3][3][5];
    float nrm[2][2][2];
};

// W2 permuted, s-pair packed over k-pairs (NO duplication, 384 KB):
// float index o = (((sp*32 + k2)*256 + t)*4 + e)
//   e=0: (k=2k2  , s=2sp  )   e=1: (k=2k2  , s=2sp+1)
//   e=2: (k=2k2+1, s=2sp  )   e=3: (k=2k2+1, s=2sp+1)
// col(s,t) = s<3 ? s*256+t : 768+3t+(s-3)
__device__ float g_W2P[64 * NPATH];

__global__ void permute_w2(const float* __restrict__ W2) {
    int o = blockIdx.x * blockDim.x + threadIdx.x;
    if (o >= 64 * NPATH) return;
    int e  = o & 3;
    int t  = (o >> 2) & 255;
    int k2 = (o >> 10) & 31;
    int sp = o >> 15;
    int k  = 2 * k2 + (e >> 1);
    int s  = 2 * sp + (e & 1);
    int col = (s < 3) ? (s * 256 + t) : (768 + 3 * t + (s - 3));
    g_W2P[o] = W2[k * NPATH + col];
}

__device__ __forceinline__ unsigned long long fma2(unsigned long long a,
                                                   unsigned long long b,
                                                   unsigned long long c) {
    unsigned long long d;
    asm("fma.rn.f32x2 %0, %1, %2, %3;" : "=l"(d) : "l"(a), "l"(b), "l"(c));
    return d;
}
__device__ __forceinline__ void unpack2(unsigned long long v, float& lo, float& hi) {
    asm("mov.b64 {%0, %1}, %2;" : "=f"(lo), "=f"(hi) : "l"(v));
}
__device__ __forceinline__ void half_bar(int ph) {
    asm volatile("bar.sync %0, %1;" :: "r"(ph + 1), "r"(256) : "memory");
}

__global__ __launch_bounds__(512, 1)
void qm9_fused(const float* __restrict__ r,
               const float* __restrict__ W1,
               const float* __restrict__ b1,
               const float* __restrict__ b2,
               float* __restrict__ out,
               const Consts C)
{
    // h duplicated per element: sh_hd[k][p] = (h, h)
    __shared__ __align__(16) float2 sh_hd[64][16];   // 8 KB
    __shared__ float sh_pp[GPTS][36];
    __shared__ float sh_rad[GPTS];
    __shared__ float sR[2][6][256];                  // per-half R exchange, 12 KB

    const int t  = threadIdx.x;
    const int tc = t & 255;      // column owner
    const int ph = t >> 8;       // point half: handles points ph*8 .. ph*8+7
    const int block0 = blockIdx.x * GPTS;

    // ---- Phase A: per-point SH + folded CG*Y*norm (threads 0..15) ----
    if (t < GPTS) {
        int pg = block0 + t;
        float x = r[pg * 3 + 0], y = r[pg * 3 + 1], z = r[pg * 3 + 2];
        float r2 = x * x + y * y + z * z;
        sh_rad[t] = sqrtf(r2);
        float inv  = rsqrtf(r2);
        float inv2 = 1.0f / r2;
        const float c0  = 0.28209479177387814f;
        const float c1  = 0.48860251190291992f;
        const float c2  = 1.09254843059207907f;
        const float c20 = 0.31539156525252005f;
        float Y[9];
        Y[0] = c0;
        Y[1] = c1 * y * inv;
        Y[2] = c1 * z * inv;
        Y[3] = c1 * x * inv;
        Y[4] = c2 * x * y * inv2;
        Y[5] = c2 * y * z * inv2;
        Y[6] = c20 * (3.0f * z * z - r2) * inv2;
        Y[7] = c2 * x * z * inv2;
        Y[8] = 0.5f * c2 * (x * x - y * y) * inv2;

        int zf = (r2 == 0.0f) ? 1 : 0;
        float s00 = C.nrm[0][0][zf], s01 = C.nrm[0][1][zf];
        float s10 = C.nrm[1][0][zf], s11 = C.nrm[1][1][zf];

        sh_pp[t][0] = C.cg000 * Y[0] * s00;
        #pragma unroll
        for (int j = 0; j < 3; j++) {
            float a = 0.f;
            #pragma unroll
            for (int k = 0; k < 3; k++) a += C.cg011[j][k] * Y[1 + k];
            sh_pp[t][1 + j] = a * s01;
        }
        #pragma unroll
        for (int i = 0; i < 3; i++) {
            float a = 0.f;
            #pragma unroll
            for (int k = 0; k < 3; k++) a += C.cg101[i][k] * Y[1 + k];
            sh_pp[t][4 + i] = a * s10;
        }
        #pragma unroll
        for (int i = 0; i < 3; i++) {
            #pragma unroll
            for (int j = 0; j < 3; j++) {
                sh_pp[t][7 + i * 3 + j] = C.cg110[i][j] * Y[0] * s11;
                float a1 = 0.f;
                #pragma unroll
                for (int k = 0; k < 3; k++) a1 += C.cg111[i][j][k] * Y[1 + k];
                sh_pp[t][16 + i * 3 + j] = a1 * s11;
                float a2 = 0.f;
                #pragma unroll
                for (int k = 0; k < 5; k++) a2 += C.cg112[i][j][k] * Y[4 + k];
                sh_pp[t][25 + i * 3 + j] = a2 * s11;
            }
        }
    }
    __syncthreads();

    // ---- Phase B: h = silu(rad*W1+b1), stored duplicated [k][p] = (h,h) ----
    {
        int p  = t & 15;
        int k0 = (t >> 4) * 2;   // t>>4 in 0..31 -> k0 in 0..62
        float rad = sh_rad[p];
        #pragma unroll
        for (int e = 0; e < 2; e++) {
            float xx = fmaf(rad, W1[k0 + e], b1[k0 + e]);
            float h = xx / (1.0f + expf(-xx));
            sh_hd[k0 + e][p] = make_float2(h, h);
        }
    }
    __syncthreads();

    // ---- Phase C: packed GEMM over s-pairs, 8 points per thread.
    // acc[j][sp] (u64) = (R_{2sp}(p), R_{2sp+1}(p)) for local point j = p - ph*8.
    unsigned long long acc[8][3];
    #pragma unroll
    for (int j = 0; j < 8; j++)
        #pragma unroll
        for (int sp = 0; sp < 3; sp++) acc[j][sp] = 0ull;

    const ulonglong2* wp = (const ulonglong2*)g_W2P + tc;       // slot stride 256
    const ulonglong2* hp = (const ulonglong2*)sh_hd + ph * 4;   // pairs of this half

    ulonglong2 wA = wp[(0 * 32 + 0) * 256];
    ulonglong2 wB = wp[(1 * 32 + 0) * 256];
    ulonglong2 wC = wp[(2 * 32 + 0) * 256];

    #pragma unroll 1
    for (int k2 = 0; k2 < 32; k2++) {
        int kn = (k2 < 31) ? (k2 + 1) : 31;
        ulonglong2 nA = wp[(0 * 32 + kn) * 256];
        ulonglong2 nB = wp[(1 * 32 + kn) * 256];
        ulonglong2 nC = wp[(2 * 32 + kn) * 256];

        #pragma unroll
        for (int q = 0; q < 4; q++) {
            ulonglong2 he = hp[(2 * k2 + 0) * 8 + q];   // k even, points (2q, 2q+1) of half
            ulonglong2 ho = hp[(2 * k2 + 1) * 8 + q];   // k odd
            acc[2 * q + 0][0] = fma2(he.x, wA.x, acc[2 * q + 0][0]);
            acc[2 * q + 0][1] = fma2(he.x, wB.x, acc[2 * q + 0][1]);
            acc[2 * q + 0][2] = fma2(he.x, wC.x, acc[2 * q + 0][2]);
            acc[2 * q + 1][0] = fma2(he.y, wA.x, acc[2 * q + 1][0]);
            acc[2 * q + 1][1] = fma2(he.y, wB.x, acc[2 * q + 1][1]);
            acc[2 * q + 1][2] = fma2(he.y, wC.x, acc[2 * q + 1][2]);
            acc[2 * q + 0][0] = fma2(ho.x, wA.y, acc[2 * q + 0][0]);
            acc[2 * q + 0][1] = fma2(ho.x, wB.y, acc[2 * q + 0][1]);
            acc[2 * q + 0][2] = fma2(ho.x, wC.y, acc[2 * q + 0][2]);
            acc[2 * q + 1][0] = fma2(ho.y, wA.y, acc[2 * q + 1][0]);
            acc[2 * q + 1][1] = fma2(ho.y, wB.y, acc[2 * q + 1][1]);
            acc[2 * q + 1][2] = fma2(ho.y, wC.y, acc[2 * q + 1][2]);
        }
        wA = nA; wB = nB; wC = nC;
    }

    // ---- Phase D: coalesced epilogue via per-half smem R-exchange ----
    float b2v[6];
    b2v[0] = b2[tc];
    b2v[1] = b2[256 + tc];
    b2v[2] = b2[512 + tc];
    b2v[3] = b2[768 + 3 * tc + 0];
    b2v[4] = b2[768 + 3 * tc + 1];
    b2v[5] = b2[768 + 3 * tc + 2];

    // Thread writes float4 #(m*256+tc) of its point's 4096-float block:
    //   row = m*16 + (tc>>4), cols = 4*(tc&15)+{0..3}
    const int tu = tc >> 4;     // 0..15
    const int c  = tc & 15;     // col chunk

    int vd0 = 0, vd1 = 0, vd2 = 0, vd3 = 0, jd0 = 0, jd1 = 0, jd2 = 0, jd3 = 0;
    if (c >= 4) {
        int base = 4 * (c - 4);
        vd0 = (base + 0) / 3; jd0 = (base + 0) - 3 * vd0;
        vd1 = (base + 1) / 3; jd1 = (base + 1) - 3 * vd1;
        vd2 = (base + 2) / 3; jd2 = (base + 2) - 3 * vd2;
        vd3 = (base + 3) / 3; jd3 = (base + 3) - 3 * vd3;
    }
    int um[4], im[4];
    #pragma unroll
    for (int m = 1; m < 4; m++) {
        int rr = (m - 1) * 16 + tu;
        um[m] = rr / 3;
        im[m] = rr - 3 * um[m];
    }

    #pragma unroll 1
    for (int j = 0; j < 8; j++) {
        float R[6];
        unpack2(acc[j][0], R[0], R[1]);
        unpack2(acc[j][1], R[2], R[3]);
        unpack2(acc[j][2], R[4], R[5]);
        #pragma unroll
        for (int s = 0; s < 6; s++) sR[ph][s][tc] = R[s] + b2v[s];
        half_bar(ph);

        const int p = ph * 8 + j;
        const float* pp = sh_pp[p];
        float* o = out + (size_t)(block0 + p) * 4096;
        const float (*sRh)[256] = sR[ph];

        #pragma unroll
        for (int m = 0; m < 4; m++) {
            float v0, v1, v2, v3;
            if (m == 0) {
                if (c < 4) {
                    const float* s0 = &sRh[0][tu * 16 + 4 * c];
                    float sc = pp[0];
                    v0 = sc * s0[0]; v1 = sc * s0[1]; v2 = sc * s0[2]; v3 = sc * s0[3];
                } else {
                    const float* s1 = &sRh[1][tu * 16];
                    v0 = pp[1 + jd0] * s1[vd0];
                    v1 = pp[1 + jd1] * s1[vd1];
                    v2 = pp[1 + jd2] * s1[vd2];
                    v3 = pp[1 + jd3] * s1[vd3];
                }
            } else {
                int u2 = um[m], i = im[m];
                if (c < 4) {
                    const float* s2 = &sRh[2][u2 * 16 + 4 * c];
                    float sc = pp[4 + i];
                    v0 = sc * s2[0]; v1 = sc * s2[1]; v2 = sc * s2[2]; v3 = sc * s2[3];
                } else {
                    const float* s3 = &sRh[3][u2 * 16];
                    const float* s4 = &sRh[4][u2 * 16];
                    const float* s5 = &sRh[5][u2 * 16];
                    const float* pa = pp + 7  + 3 * i;
                    const float* pb = pp + 16 + 3 * i;
                    const float* pc = pp + 25 + 3 * i;
                    v0 = pa[jd0] * s3[vd0] + pb[jd0] * s4[vd0] + pc[jd0] * s5[vd0];
                    v1 = pa[jd1] * s3[vd1] + pb[jd1] * s4[vd1] + pc[jd1] * s5[vd1];
                    v2 = pa[jd2] * s3[vd2] + pb[jd2] * s4[vd2] + pc[jd2] * s5[vd2];
                    v3 = pa[jd3] * s3[vd3] + pb[jd3] * s4[vd3] + pc[jd3] * s5[vd3];
                }
            }
            ((float4*)o)[m * 256 + tc] = make_float4(v0, v1, v2, v3);
        }
        half_bar(ph);
    }
}

// ===========================================================================
// Host: exact replication of the reference real-3j / norm constants.
// ===========================================================================
static double dfact_(int n) { double r = 1.0; for (int i = 2; i <= n; i++) r *= i; return r; }

static double su2_cg_(int j1, int m1, int j2, int m2, int j3, int m3) {
    if (m3 != m1 + m2) return 0.0;
    int vmin = std::max(std::max(-j1 + j2 + m3, -j1 + m1), 0);
    int vmax = std::min(std::min(j2 + j3 + m1, j3 - j1 + j2), j3 + m3);
    double c = sqrt((2 * j3 + 1) * dfact_(j3 + j1 - j2) * dfact_(j3 - j1 + j2) *
                    dfact_(j1 + j2 - j3) / dfact_(j1 + j2 + j3 + 1)) *
               sqrt(dfact_(j3 + m3) * dfact_(j3 - m3) /
                    (dfact_(j1 + m1) * dfact_(j1 - m1) * dfact_(j2 + m2) * dfact_(j2 - m2)));
    double s = 0.0;
    for (int v = vmin; v <= vmax; v++) {
        double sg = ((v + j2 + m2) & 1) ? -1.0 : 1.0;
        s += sg * dfact_(j2 + j3 + m1 - v) * dfact_(j1 - m1 + v) /
             (dfact_(v) * dfact_(j3 - j1 + j2 - v) * dfact_(j3 + m3 - v) *
              dfact_(v + j1 - j2 - m3));
    }
    return c * s;
}

static void Qmat_(int l, std::complex<double> q[5][5]) {
    for (int i = 0; i < 5; i++) for (int j = 0; j < 5; j++) q[i][j] = 0.0;
    q[l][l] = 1.0;
    double s2 = 1.0 / sqrt(2.0);
    for (int m = 1; m <= l; m++) {
        double pm = (m & 1) ? -1.0 : 1.0;
        q[l + m][l - m] = s2;
        q[l + m][l + m] = pm * s2;
        q[l - m][l - m] = std::complex<double>(0.0, s2);
        q[l - m][l + m] = std::complex<double>(0.0, -pm * s2);
    }
}

static void real3j_(int l1, int l2, int l3, double outc[5][5][5]) {
    int d1 = 2 * l1 + 1, d2 = 2 * l2 + 1, d3 = 2 * l3 + 1;
    double w[5][5][5];
    for (int i = 0; i < 5; i++) for (int j = 0; j < 5; j++) for (int k = 0; k < 5; k++)
        w[i][j][k] = 0.0;
    for (int m1 = -l1; m1 <= l1; m1++)
        for (int m2 = -l2; m2 <= l2; m2++) {
            int m3 = -(m1 + m2);
            if (m3 < -l3 || m3 > l3) continue;
            double sg = ((l1 - l2 + m1 + m2) & 1) ? -1.0 : 1.0;
            w[m1 + l1][m2 + l2][m3 + l3] =
                sg / sqrt((double)(2 * l3 + 1)) * su2_cg_(l1, m1, l2, m2, l3, -m3);
        }
    std::complex<double> q1[5][5], q2[5][5], q3[5][5];
    Qmat_(l1, q1); Qmat_(l2, q2); Qmat_(l3, q3);
    std::complex<double> Cc[5][5][5];
    for (int a = 0; a < d1; a++)
        for (int b = 0; b < d2; b++)
            for (int c = 0; c < d3; c++) {
                std::complex<double> s = 0.0;
                for (int i = 0; i < d1; i++)
                    for (int j = 0; j < d2; j++)
                        for (int k = 0; k < d3; k++)
                            s += q1[a][i] * q2[b][j] * q3[c][k] * w[i][j][k];
                Cc[a][b][c] = s;
            }
    double maxv = 0.0;
    for (int a = 0; a < d1; a++) for (int b = 0; b < d2; b++) for (int c = 0; c < d3; c++)
        maxv = std::max(maxv, std::abs(Cc[a][b][c]));
    std::complex<double> ph = 0.0;
    for (int a = 0; a < d1 && ph == 0.0; a++)
        for (int b = 0; b < d2 && ph == 0.0; b++)
            for (int c = 0; c < d3 && ph == 0.0; c++)
                if (std::abs(Cc[a][b][c]) >= maxv * (1.0 - 1e-9)) ph = Cc[a][b][c];
    for (int i = 0; i < 5; i++) for (int j = 0; j < 5; j++) for (int k = 0; k < 5; k++)
        outc[i][j][k] = 0.0;
    if (std::abs(ph) < 1e-12) {
        for (int a = 0; a < d1; a++) for (int b = 0; b < d2; b++) for (int c = 0; c < d3; c++)
            outc[a][b][c] = Cc[a][b][c].real();
    } else {
        std::complex<double> u = ph / std::abs(ph);
        for (int a = 0; a < d1; a++) for (int b = 0; b < d2; b++) for (int c = 0; c < d3; c++)
            outc[a][b][c] = (Cc[a][b][c] / u).real();
    }
}

extern "C" void kernel_launch(void* const* d_in, const int* in_sizes, int n_in,
                              void* d_out, int out_size) {
    const float* r  = (const float*)d_in[0];
    const float* W1 = (const float*)d_in[1];
    const float* b1 = (const float*)d_in[2];
    const float* W2 = (const float*)d_in[3];
    const float* b2 = (const float*)d_in[4];
    float* out = (float*)d_out;

    Consts C;
    double tmp[5][5][5];
    real3j_(0, 0, 0, tmp); C.cg000 = (float)tmp[0][0][0];
    real3j_(0, 1, 1, tmp);
    for (int j = 0; j < 3; j++) for (int k = 0; k < 3; k++) C.cg011[j][k] = (float)tmp[0][j][k];
    real3j_(1, 0, 1, tmp);
    for (int i = 0; i < 3; i++) for (int k = 0; k < 3; k++) C.cg101[i][k] = (float)tmp[i][0][k];
    real3j_(1, 1, 0, tmp);
    for (int i = 0; i < 3; i++) for (int j = 0; j < 3; j++) C.cg110[i][j] = (float)tmp[i][j][0];
    real3j_(1, 1, 1, tmp);
    for (int i = 0; i < 3; i++) for (int j = 0; j < 3; j++) for (int k = 0; k < 3; k++)
        C.cg111[i][j][k] = (float)tmp[i][j][k];
    real3j_(1, 1, 2, tmp);
    for (int i = 0; i < 3; i++) for (int j = 0; j < 3; j++) for (int k = 0; k < 5; k++)
        C.cg112[i][j][k] = (float)tmp[i][j][k];

    const double fourpi = 4.0 * M_PI;
    double nse[2] = {32.0, 64.0};
    for (int i = 0; i < 2; i++)
        for (int j = 0; j < 2; j++) {
            double li = (j == 0) ? 0.0 : 1.0;
            double lm = sqrt(2.0 * li + 1.0) * sqrt(fourpi);
            C.nrm[i][j][0] = (float)(lm / sqrt(nse[i]));
            C.nrm[i][j][1] = (float)(lm / sqrt(16.0));
        }

    permute_w2<<<(64 * NPATH + 255) / 256, 256>>>(W2);
    qm9_fused<<<NBLK, 512>>>(r, W1, b1, b2, out, C);
}